// round 8
// baseline (speedup 1.0000x reference)
#include <cuda_runtime.h>

#define THREADS 256
#define WARPS   (THREADS / 32)
#define D       128                  // feature dim (f32) = 32 lanes * float4
#define BLOCKS_PER_SM 6
#define ROWS_PER_BLOCK 256           // fine-grained: ~4.4 waves -> HW load balancing
#define UNROLL  4

__global__ void zero_out_kernel(float* __restrict__ out, int n) {
    int i = blockIdx.x * blockDim.x + threadIdx.x;
    if (i < n) out[i] = 0.0f;
}

__device__ __forceinline__ void flush(float* __restrict__ out, int seg, int lane, float4 acc) {
    float* o = out + (long long)seg * D + lane * 4;
    atomicAdd(o + 0, acc.x);
    atomicAdd(o + 1, acc.y);
    atomicAdd(o + 2, acc.z);
    atomicAdd(o + 3, acc.w);
}

__device__ __forceinline__ void merge(int s, float4 v, int& cur, float4& acc,
                                      float* __restrict__ out, int lane) {
    if (__builtin_expect(s != cur, 0)) {
        flush(out, cur, lane, acc);
        cur = s;
        acc = v;
    } else {
        acc.x += v.x; acc.y += v.y; acc.z += v.z; acc.w += v.w;
    }
}

__global__ __launch_bounds__(THREADS, BLOCKS_PER_SM) void segsum_kernel(
    const float4* __restrict__ feat4,      // [rows, 32] float4
    const int*    __restrict__ sids,       // [rows]
    float*        __restrict__ out,        // [num_segments, 128]
    int rows)
{
    const int lane = threadIdx.x & 31;
    const int warp = threadIdx.x >> 5;

    int row0    = blockIdx.x * ROWS_PER_BLOCK;
    int row_end = row0 + ROWS_PER_BLOCK;
    if (row_end > rows) row_end = rows;

    int r = row0 + warp;
    if (r >= row_end) return;

    float4 acc = make_float4(0.f, 0.f, 0.f, 0.f);
    int cur = __ldg(&sids[r]);

    // Unrolled main loop: all UNROLL loads issued back-to-back (MLP), then merge.
    for (; r + (UNROLL - 1) * WARPS < row_end; r += UNROLL * WARPS) {
        float4 v0 = __ldcs(&feat4[(long long)(r + 0 * WARPS) * 32 + lane]);
        float4 v1 = __ldcs(&feat4[(long long)(r + 1 * WARPS) * 32 + lane]);
        float4 v2 = __ldcs(&feat4[(long long)(r + 2 * WARPS) * 32 + lane]);
        float4 v3 = __ldcs(&feat4[(long long)(r + 3 * WARPS) * 32 + lane]);
        int s0 = __ldcs(&sids[r + 0 * WARPS]);
        int s1 = __ldcs(&sids[r + 1 * WARPS]);
        int s2 = __ldcs(&sids[r + 2 * WARPS]);
        int s3 = __ldcs(&sids[r + 3 * WARPS]);

        merge(s0, v0, cur, acc, out, lane);
        merge(s1, v1, cur, acc, out, lane);
        merge(s2, v2, cur, acc, out, lane);
        merge(s3, v3, cur, acc, out, lane);
    }

    // Remainder
    for (; r < row_end; r += WARPS) {
        float4 v = __ldcs(&feat4[(long long)r * 32 + lane]);
        int    s = __ldcs(&sids[r]);
        merge(s, v, cur, acc, out, lane);
    }

    flush(out, cur, lane, acc);
}

extern "C" void kernel_launch(void* const* d_in, const int* in_sizes, int n_in,
                              void* d_out, int out_size)
{
    const float4* feat4 = (const float4*)d_in[0];   // feat [1e6, 128] f32
    const int*    sids  = (const int*)d_in[1];      // segment_ids [1e6] i32
    float*        out   = (float*)d_out;            // [4096, 128] f32

    const int rows = in_sizes[0] / D;

    // Zero-init output (d_out is poisoned before timing).
    {
        int blocks = (out_size + THREADS - 1) / THREADS;
        zero_out_kernel<<<blocks, THREADS>>>(out, out_size);
    }

    // Fine-grained blocks: HW block distributor provides dynamic load balancing
    // across ~4.4 waves, shrinking the finish-skew tail to <= one block-time.
    int grid = (rows + ROWS_PER_BLOCK - 1) / ROWS_PER_BLOCK;

    segsum_kernel<<<grid, THREADS>>>(feat4, sids, out, rows);
}

// round 9
// speedup vs baseline: 1.0214x; 1.0214x over previous
#include <cuda_runtime.h>

#define THREADS 256
#define WARPS   (THREADS / 32)
#define D       128                  // feature dim (f32) = 32 lanes * float4
#define BLOCKS_PER_SM 6
#define ROWS_PER_BLOCK 256           // fine-grained: ~4.4 waves, HW load balancing
#define QUAD 4                       // rows per warp-iteration (consecutive)

__global__ void zero_out_kernel(float* __restrict__ out, int n) {
    int i = blockIdx.x * blockDim.x + threadIdx.x;
    if (i < n) out[i] = 0.0f;
}

__device__ __forceinline__ void flush(float* __restrict__ out, int seg, int lane, float4 acc) {
    float* o = out + (long long)seg * D + lane * 4;
    atomicAdd(o + 0, acc.x);
    atomicAdd(o + 1, acc.y);
    atomicAdd(o + 2, acc.z);
    atomicAdd(o + 3, acc.w);
}

__device__ __forceinline__ void merge(int s, float4 v, int& cur, float4& acc,
                                      float* __restrict__ out, int lane) {
    if (__builtin_expect(s != cur, 0)) {
        flush(out, cur, lane, acc);
        cur = s;
        acc = v;
    } else {
        acc.x += v.x; acc.y += v.y; acc.z += v.z; acc.w += v.w;
    }
}

__global__ __launch_bounds__(THREADS, BLOCKS_PER_SM) void segsum_kernel(
    const float4* __restrict__ feat4,      // [rows, 32] float4
    const int*    __restrict__ sids,       // [rows]
    float*        __restrict__ out,        // [num_segments, 128]
    int rows)
{
    const int lane = threadIdx.x & 31;
    const int warp = threadIdx.x >> 5;

    int row0    = blockIdx.x * ROWS_PER_BLOCK;
    int row_end = row0 + ROWS_PER_BLOCK;
    if (row_end > rows) row_end = rows;

    // Warp owns consecutive quads of rows: [base, base+3], stride QUAD*WARPS.
    int base = row0 + warp * QUAD;
    if (base >= row_end) return;

    float4 acc = make_float4(0.f, 0.f, 0.f, 0.f);
    int cur = __ldg(&sids[base]);

    for (; base + (QUAD - 1) < row_end; base += QUAD * WARPS) {
        // One vector sid load for 4 rows (16B-aligned: base % 4 == 0).
        int4 s = __ldcs((const int4*)(sids + base));
        // 4 contiguous 512B row loads -> 2KB contiguous per warp-iteration.
        float4 v0 = __ldcs(&feat4[(long long)(base + 0) * 32 + lane]);
        float4 v1 = __ldcs(&feat4[(long long)(base + 1) * 32 + lane]);
        float4 v2 = __ldcs(&feat4[(long long)(base + 2) * 32 + lane]);
        float4 v3 = __ldcs(&feat4[(long long)(base + 3) * 32 + lane]);

        if (__builtin_expect(s.x == cur && s.w == cur, 1)) {
            // Fast path: whole quad belongs to the running segment.
            acc.x += v0.x + v1.x + v2.x + v3.x;
            acc.y += v0.y + v1.y + v2.y + v3.y;
            acc.z += v0.z + v1.z + v2.z + v3.z;
            acc.w += v0.w + v1.w + v2.w + v3.w;
        } else {
            merge(s.x, v0, cur, acc, out, lane);
            merge(s.y, v1, cur, acc, out, lane);
            merge(s.z, v2, cur, acc, out, lane);
            merge(s.w, v3, cur, acc, out, lane);
        }
    }

    // Remainder rows (<QUAD) of this warp's last quad, if chunk not multiple of 4.
    for (; base < row_end; ++base) {
        float4 v = __ldcs(&feat4[(long long)base * 32 + lane]);
        int    sv = __ldg(&sids[base]);
        merge(sv, v, cur, acc, out, lane);
    }

    flush(out, cur, lane, acc);
}

extern "C" void kernel_launch(void* const* d_in, const int* in_sizes, int n_in,
                              void* d_out, int out_size)
{
    const float4* feat4 = (const float4*)d_in[0];   // feat [1e6, 128] f32
    const int*    sids  = (const int*)d_in[1];      // segment_ids [1e6] i32
    float*        out   = (float*)d_out;            // [4096, 128] f32

    const int rows = in_sizes[0] / D;

    // Zero-init output (d_out is poisoned before timing).
    {
        int blocks = (out_size + THREADS - 1) / THREADS;
        zero_out_kernel<<<blocks, THREADS>>>(out, out_size);
    }

    int grid = (rows + ROWS_PER_BLOCK - 1) / ROWS_PER_BLOCK;
    segsum_kernel<<<grid, THREADS>>>(feat4, sids, out, rows);
}